// round 7
// baseline (speedup 1.0000x reference)
#include <cuda_runtime.h>
#include <cuda_fp16.h>
#include <cuda_bf16.h>

// ResidualGridVolume: out[n,c] = trilinear((base+detail)[c], xyz[n]/1.5), C=28, R=128.
//
// R5 learning: 64B-padded voxels (134 MB) overflow L2 (126 MB) -> random access
// thrashes -> 945 MB DRAM traffic in sample (74% DRAM busy). Fix: UNPADDED
// 56 B voxels = 112 MB, truly L2-resident. 56 % 16 != 0, so use 8B chunks:
// OCT-cooperative gather (8 threads/point, thread j<7 owns channels 4j..4j+3,
// uint2 loads at voxel*56 + 8j, always 8B-aligned). One warp load per corner
// covers 4 points' full 56B spans (~5.5 lines) -> ~11 wf/point, same L1 cost
// as R5, while volume DRAM misses go to ~0.

static constexpr int R   = 128;
static constexpr int R3  = R * R * R;     // 2,097,152 voxels
static constexpr int CH  = 28;            // 1 density + 27 SH (56 B fp16/voxel)

// 112 MB scratch: __device__ global (no runtime allocation).
__device__ __align__(256) __half g_volh[(size_t)R3 * CH];

// ---------------------------------------------------------------------------
// Kernel 1: fuse base+detail -> fp16, voxel-major, 56 B voxels (no padding).
// Streaming input reads (__ldcs) keep L2 for the volume; normal stores make
// the volume L2-resident. 7x uint2 stores (8B-aligned for every voxel).
// ---------------------------------------------------------------------------
__global__ void fuse_transpose_kernel(const float* __restrict__ base_density,
                                      const float* __restrict__ base_sh,
                                      const float* __restrict__ detail_density,
                                      const float* __restrict__ detail_sh) {
    int v = blockIdx.x * blockDim.x + threadIdx.x;
    if (v >= R3) return;

    __half h[CH];
    h[0] = __float2half_rn(__ldcs(base_density + v) + __ldcs(detail_density + v));
#pragma unroll
    for (int c = 0; c < 27; c++) {
        size_t off = (size_t)c * R3 + (size_t)v;
        h[c + 1] = __float2half_rn(__ldcs(base_sh + off) + __ldcs(detail_sh + off));
    }

    uint2* dst = reinterpret_cast<uint2*>(g_volh + (size_t)v * CH);
#pragma unroll
    for (int i = 0; i < 7; i++)
        dst[i] = reinterpret_cast<const uint2*>(h)[i];
}

// ---------------------------------------------------------------------------
// Kernel 2: oct-cooperative trilinear gather. 8 threads per point; thread
// j = tid&7 (j<7) owns channels 4j..4j+3 via one uint2 per corner. Weight
// math is redundant within the oct (costs no extra warp instructions).
// ---------------------------------------------------------------------------
__global__ void __launch_bounds__(256)
sample_kernel(const float* __restrict__ xyz, float* __restrict__ out, int N) {
    int t = blockIdx.x * blockDim.x + threadIdx.x;
    int p = t >> 3;          // point index (4 points per warp)
    int j = t & 7;           // chunk index; j==7 is idle
    if (p >= N) return;

    // Oct-broadcast reads of this point's coords (same line for whole oct).
    const float inv_bound = 1.0f / 1.5f;
    float gx = __ldg(xyz + 3 * p + 0) * inv_bound;
    float gy = __ldg(xyz + 3 * p + 1) * inv_bound;
    float gz = __ldg(xyz + 3 * p + 2) * inv_bound;

    // align_corners=True: pix = (g + 1) * 0.5 * (size - 1)
    float px = (gx + 1.0f) * 0.5f * 127.0f;
    float py = (gy + 1.0f) * 0.5f * 127.0f;
    float pz = (gz + 1.0f) * 0.5f * 127.0f;

    float fx0 = floorf(px), fy0 = floorf(py), fz0 = floorf(pz);
    float fx = px - fx0, fy = py - fy0, fz = pz - fz0;

    // Inputs are interior (|g| <= 0.99); clamps are safety only.
    int x0 = min(max((int)fx0, 0), R - 2);
    int y0 = min(max((int)fy0, 0), R - 2);
    int z0 = min(max((int)fz0, 0), R - 2);

    float wx1 = fx, wx0 = 1.0f - fx;
    float wy1 = fy, wy0 = 1.0f - fy;
    float wz1 = fz, wz0 = 1.0f - fz;

    float w[8];
    w[0] = wz0 * wy0 * wx0;
    w[1] = wz0 * wy0 * wx1;
    w[2] = wz0 * wy1 * wx0;
    w[3] = wz0 * wy1 * wx1;
    w[4] = wz1 * wy0 * wx0;
    w[5] = wz1 * wy0 * wx1;
    w[6] = wz1 * wy1 * wx0;
    w[7] = wz1 * wy1 * wx1;

    const unsigned OX = CH;               // +1 in x (in halves)
    const unsigned OY = R * CH;           // +1 in y
    const unsigned OZ = R * R * CH;       // +1 in z
    unsigned base = (((unsigned)z0 * R + (unsigned)y0) * R + (unsigned)x0) * CH
                    + 4u * (unsigned)j;   // this thread's channel chunk

    unsigned offs[8];
    offs[0] = base;
    offs[1] = base + OX;
    offs[2] = base + OY;
    offs[3] = base + OY + OX;
    offs[4] = base + OZ;
    offs[5] = base + OZ + OX;
    offs[6] = base + OZ + OY;
    offs[7] = base + OZ + OY + OX;

    bool active = (j < 7);

    // Issue all 8 corner loads first (MLP = 8), then accumulate.
    uint2 q[8];
#pragma unroll
    for (int k = 0; k < 8; k++) {
        q[k] = active
             ? __ldg(reinterpret_cast<const uint2*>(g_volh + (size_t)offs[k]))
             : make_uint2(0u, 0u);
    }

    float acc0 = 0.f, acc1 = 0.f, acc2 = 0.f, acc3 = 0.f;
#pragma unroll
    for (int k = 0; k < 8; k++) {
        float wk = w[k];
        __half2 h0 = *reinterpret_cast<__half2*>(&q[k].x);
        __half2 h1 = *reinterpret_cast<__half2*>(&q[k].y);
        float2 f0 = __half22float2(h0);
        float2 f1 = __half22float2(h1);
        acc0 = fmaf(wk, f0.x, acc0);
        acc1 = fmaf(wk, f0.y, acc1);
        acc2 = fmaf(wk, f1.x, acc2);
        acc3 = fmaf(wk, f1.y, acc3);
    }

    // Output row = 112 B; thread j stores bytes [16j, 16j+16) of row p.
    // Always 16B-aligned. Streaming: don't evict the L2-resident volume.
    if (active) {
        float4* o = reinterpret_cast<float4*>(out + (size_t)p * CH + 4 * j);
        __stcs(o, make_float4(acc0, acc1, acc2, acc3));
    }
}

// ---------------------------------------------------------------------------
// Launch. Inputs in metadata order:
//   [0] xyz (N*3), [1] base_density (128^3), [2] base_sh (27*128^3),
//   [3] detail_density, [4] detail_sh. Output: float32, N*28.
// ---------------------------------------------------------------------------
extern "C" void kernel_launch(void* const* d_in, const int* in_sizes, int n_in,
                              void* d_out, int out_size) {
    const float* xyz            = (const float*)d_in[0];
    const float* base_density   = (const float*)d_in[1];
    const float* base_sh        = (const float*)d_in[2];
    const float* detail_density = (const float*)d_in[3];
    const float* detail_sh      = (const float*)d_in[4];
    float* out = (float*)d_out;

    int N = in_sizes[0] / 3;

    {
        int threads = 256;
        int blocks = (R3 + threads - 1) / threads;
        fuse_transpose_kernel<<<blocks, threads>>>(base_density, base_sh,
                                                   detail_density, detail_sh);
    }
    {
        long long total = 8LL * N;   // 8 threads per point
        int threads = 256;
        int blocks = (int)((total + threads - 1) / threads);
        sample_kernel<<<blocks, threads>>>(xyz, out, N);
    }
}